// round 5
// baseline (speedup 1.0000x reference)
#include <cuda_runtime.h>

#define HW 1024

// Scratch buffers
__device__ float g_qkv[8 * 192 * HW];        // [b][192][1024]; q pre-scaled by dkh^-0.5*log2e
__device__ float g_pacc[2 * 8 * 64 * HW];    // [whalf][b][64][1024] partial softmax-weighted V sums
__device__ float g_pssum[2 * 8 * 8 * HW];    // [whalf][b][n][1024] partial exp sums

typedef unsigned long long u64;

__device__ __forceinline__ u64 fma2(u64 a, u64 b, u64 c) {
  u64 d; asm("fma.rn.f32x2 %0,%1,%2,%3;" : "=l"(d) : "l"(a), "l"(b), "l"(c)); return d;
}
__device__ __forceinline__ u64 add2(u64 a, u64 b) {
  u64 d; asm("add.rn.f32x2 %0,%1,%2;" : "=l"(d) : "l"(a), "l"(b)); return d;
}
__device__ __forceinline__ u64 pack2(float lo, float hi) {
  u64 d; asm("mov.b64 %0,{%1,%2};" : "=l"(d) : "f"(lo), "f"(hi)); return d;
}
__device__ __forceinline__ void unpack2(u64 v, float& lo, float& hi) {
  asm("mov.b64 {%0,%1},%2;" : "=f"(lo), "=f"(hi) : "l"(v));
}
__device__ __forceinline__ float ex2f(float x) {
  float y; asm("ex2.approx.ftz.f32 %0,%1;" : "=f"(y) : "f"(x)); return y;
}

// ---------------------------------------------------------------------------
// Fused prep: blocks [0,128) do 3x3 conv via f32x2 over vertical pixel pairs
// (out ch 0..63); blocks [128,512) do the qkv 1x1 projection into g_qkv.
// 256 threads, 48KB dynamic smem, 3 blocks/SM (reg cap 85).
// ---------------------------------------------------------------------------
__global__ __launch_bounds__(256, 3) void prep_kernel(
    const float* __restrict__ x,
    const float* __restrict__ conv_w, const float* __restrict__ conv_b,
    const float* __restrict__ qkv_w, const float* __restrict__ qkv_b,
    float* __restrict__ out, float* __restrict__ qkv_out) {
  extern __shared__ char smraw[];
  int blk = blockIdx.x;
  int t = threadIdx.x;

  if (blk < 128) {
    // ---------------- conv 3x3, pad 1, f32x2 over y-pairs ----------------
    // wdup: [4 o][64 c][9] duplicated u64 (18432B)
    // xsdup: 2-channel chunk, [2][33 rows][34 cols] u64 (17952B)
    //   entry (r+1, xc+1) = (x[r][xc], x[r+1][xc]); r in [-1,31]
    u64* wdup = (u64*)smraw;
    u64* xsdup = wdup + 2304;
    int b = blk >> 4, og = blk & 15;

    const float* wog = conv_w + og * 2304;  // 4 oc x 64 c x 9 contiguous
    for (int i = t; i < 2304; i += 256) {
      float wv = wog[i];
      wdup[i] = pack2(wv, wv);
    }

    int xcol = t & 31, m0 = t >> 5;  // x-col; warp's base y-pair (m0, m0+8)
    u64 acc[4][2];
#pragma unroll
    for (int o = 0; o < 4; o++) { acc[o][0] = 0ull; acc[o][1] = 0ull; }

    for (int c0 = 0; c0 < 64; c0 += 2) {
      __syncthreads();
      for (int e = t; e < 2244; e += 256) {
        int cc = (e >= 1122) ? 1 : 0;
        int rem = e - cc * 1122;
        int ridx = rem / 34;
        int col = rem - ridx * 34;
        int r = ridx - 1, xc = col - 1;
        const float* xp = x + (b * 64 + c0 + cc) * HW;
        bool xok = ((unsigned)xc < 32u);
        float lo = (xok && r >= 0) ? xp[r * 32 + xc] : 0.f;
        float hi = (xok && r <= 30) ? xp[(r + 1) * 32 + xc] : 0.f;
        xsdup[e] = pack2(lo, hi);
      }
      __syncthreads();

#pragma unroll
      for (int cc = 0; cc < 2; cc++) {
        const u64* xcs = xsdup + cc * 1122;
        u64 v[2][9];
#pragma unroll
        for (int pi = 0; pi < 2; pi++) {
          int m = m0 + pi * 8;
          const u64* base = xcs + 2 * m * 34 + xcol;
#pragma unroll
          for (int kh = 0; kh < 3; kh++)
#pragma unroll
            for (int kw = 0; kw < 3; kw++)
              v[pi][kh * 3 + kw] = base[kh * 34 + kw];
        }
        const u64* wc = wdup + (c0 + cc) * 9;
#pragma unroll
        for (int o = 0; o < 4; o++) {
          u64 w0 = wc[o * 576 + 0], w1 = wc[o * 576 + 1], w2 = wc[o * 576 + 2];
          u64 w3 = wc[o * 576 + 3], w4 = wc[o * 576 + 4], w5 = wc[o * 576 + 5];
          u64 w6 = wc[o * 576 + 6], w7 = wc[o * 576 + 7], w8 = wc[o * 576 + 8];
#pragma unroll
          for (int pi = 0; pi < 2; pi++) {
            u64 a = acc[o][pi];
            a = fma2(v[pi][0], w0, a); a = fma2(v[pi][1], w1, a);
            a = fma2(v[pi][2], w2, a); a = fma2(v[pi][3], w3, a);
            a = fma2(v[pi][4], w4, a); a = fma2(v[pi][5], w5, a);
            a = fma2(v[pi][6], w6, a); a = fma2(v[pi][7], w7, a);
            a = fma2(v[pi][8], w8, a);
            acc[o][pi] = a;
          }
        }
      }
    }

#pragma unroll
    for (int o = 0; o < 4; o++) {
      int oc = og * 4 + o;
      float bb = conv_b[oc];
      float* ob = out + (b * 128 + oc) * HW;
#pragma unroll
      for (int pi = 0; pi < 2; pi++) {
        int m = m0 + pi * 8;
        float lo, hi; unpack2(acc[o][pi], lo, hi);
        ob[(2 * m) * 32 + xcol] = lo + bb;
        ob[(2 * m + 1) * 32 + xcol] = hi + bb;
      }
    }
  } else {
    // ---------------- qkv 1x1 projection ----------------
    float* xs = (float*)smraw;               // [64][128] 32KB
    u64* ws2 = (u64*)(smraw + 32768);        // [64][32]  16KB
    int r = blk - 128;
    int b = r / 48;
    int rem = r - b * 48;
    int og = rem >> 3, pt = rem & 7;
    int p0 = pt * 128;

    for (int i = t; i < 64 * 128; i += 256) {
      int c = i >> 7, pp = i & 127;
      xs[i] = x[(b * 64 + c) * HW + p0 + pp];
    }
    for (int i = t; i < 64 * 32; i += 256) {
      int c = i >> 5, o = i & 31;
      float wv = qkv_w[(og * 32 + o) * 64 + c];
      ws2[i] = pack2(wv, wv);
    }
    __syncthreads();

    int oi = t >> 5, pi = t & 31;
    u64 acc2[4][2];
#pragma unroll
    for (int a = 0; a < 4; a++) { acc2[a][0] = 0ull; acc2[a][1] = 0ull; }

    for (int c0 = 0; c0 < 64; c0 += 4) {
      u64 xv[4][2], wv[4][4];
#pragma unroll
      for (int cc = 0; cc < 4; cc++) {
        xv[cc][0] = *(const u64*)(xs + (c0 + cc) * 128 + pi * 2);
        xv[cc][1] = *(const u64*)(xs + (c0 + cc) * 128 + 64 + pi * 2);
      }
#pragma unroll
      for (int cc = 0; cc < 4; cc++)
#pragma unroll
        for (int a = 0; a < 4; a++) wv[cc][a] = ws2[(c0 + cc) * 32 + oi * 4 + a];
#pragma unroll
      for (int cc = 0; cc < 4; cc++)
#pragma unroll
        for (int a = 0; a < 4; a++) {
          acc2[a][0] = fma2(wv[cc][a], xv[cc][0], acc2[a][0]);
          acc2[a][1] = fma2(wv[cc][a], xv[cc][1], acc2[a][1]);
        }
    }

#pragma unroll
    for (int a = 0; a < 4; a++) {
      int o = og * 32 + oi * 4 + a;
      float bb = qkv_b[o];
      float sc = (o < 64) ? (0.35355339059327373f * 1.4426950408889634f) : 1.f;
      float* ob = qkv_out + (b * 192 + o) * HW + p0;
#pragma unroll
      for (int k = 0; k < 2; k++) {
        float lo, hi; unpack2(acc2[a][k], lo, hi);
        *(float2*)(ob + 64 * k + pi * 2) = make_float2(sc * (lo + bb), sc * (hi + bb));
      }
    }
  }
}

// ---------------------------------------------------------------------------
// Attention partials. grid (64 bn, 2 rowhalf, 2 whalf), block 256.
// Thread owns row pair (i0,i0+1); block covers j's with w2 in its half.
// Writes partial exp-sums and exp-weighted V sums; proj merges + divides.
// ---------------------------------------------------------------------------
#define AT_KD    0
#define AT_VD    32768
#define AT_RWT   65536                   // 256 pairs * 17 u64 = 34816
#define AT_RELW  (65536 + 34816)         // 504 floats
#define AT_RELHD (AT_RELW + 2016)        // 504 u64
#define AT_SMEM  (AT_RELHD + 4032)       // 106400 bytes -> 2 blocks/SM

__global__ __launch_bounds__(256) void attn_kernel(
    const float* __restrict__ qkv,
    const float* __restrict__ relw, const float* __restrict__ relh,
    float* __restrict__ pacc, float* __restrict__ pssum) {
  extern __shared__ char sm[];
  int t = threadIdx.x;
  int bn = blockIdx.x;
  int b = bn >> 3, n = bn & 7;
  int rowhalf = blockIdx.y;
  int whalf = blockIdx.z;

  const float* qb = qkv + (b * 192 + n * 8) * HW;
  const float* kb = qkv + (b * 192 + 64 + n * 8) * HW;
  const float* vb = qkv + (b * 192 + 128 + n * 8) * HW;

  // stage this w-half of K,V duplicated: jl = h2*16 + w2l
  u64* kdup = (u64*)(sm + AT_KD);
  u64* vdup = (u64*)(sm + AT_VD);
  for (int e = t; e < 4096; e += 256) {
    int jl = e >> 3, d = e & 7;
    int h2 = jl >> 4, w2l = jl & 15;
    int j = h2 * 32 + whalf * 16 + w2l;
    float kv = kb[d * HW + j];
    float vv = vb[d * HW + j];
    kdup[jl * 8 + d] = pack2(kv, kv);
    vdup[jl * 8 + d] = pack2(vv, vv);
  }
  float* s_relw = (float*)(sm + AT_RELW);
  for (int e = t; e < 504; e += 256) {
    s_relw[e] = relw[e];
    float rv = relh[e];
    *(u64*)(sm + AT_RELHD + e * 8) = pack2(rv, rv);
  }
  __syncthreads();

  int p = t;
  int i0 = rowhalf * 512 + 2 * p;
  int h1 = i0 >> 5, w1 = i0 & 31;   // even i0: rows share h1

  float qlo[8], qhi[8];
  u64 q2[8];
#pragma unroll
  for (int d = 0; d < 8; d++) {
    qlo[d] = qb[d * HW + i0];
    qhi[d] = qb[d * HW + i0 + 1];
    q2[d] = pack2(qlo[d], qhi[d]);
  }

  // per-pair rw table for this w-half
  u64* rwrow = (u64*)(sm + AT_RWT) + p * 17;
  for (int w2l = 0; w2l < 16; w2l++) {
    int w2 = whalf * 16 + w2l;
    const float* r0 = s_relw + (w2 - w1 + 31) * 8;
    const float* r1 = r0 - 8;
    float a = 0.f, c = 0.f;
#pragma unroll
    for (int d = 0; d < 8; d++) { a += qlo[d] * r0[d]; c += qhi[d] * r1[d]; }
    rwrow[w2l] = pack2(a, c);
  }

  u64 acc[8], ssum = 0ull;
#pragma unroll
  for (int d = 0; d < 8; d++) acc[d] = 0ull;

  for (int h2 = 0; h2 < 32; h2++) {
    const u64* rhp = (const u64*)(sm + AT_RELHD) + (h2 - h1 + 31) * 8;
    u64 rh2 = 0ull;
#pragma unroll
    for (int d = 0; d < 8; d++) rh2 = fma2(q2[d], rhp[d], rh2);

#pragma unroll 4
    for (int w2l = 0; w2l < 16; w2l++) {
      int jl = h2 * 16 + w2l;
      const ulonglong2* kj = (const ulonglong2*)(kdup + jl * 8);
      ulonglong2 k0 = kj[0], k1 = kj[1], k2 = kj[2], k3 = kj[3];
      u64 s2 = add2(rwrow[w2l], rh2);
      s2 = fma2(q2[0], k0.x, s2); s2 = fma2(q2[1], k0.y, s2);
      s2 = fma2(q2[2], k1.x, s2); s2 = fma2(q2[3], k1.y, s2);
      s2 = fma2(q2[4], k2.x, s2); s2 = fma2(q2[5], k2.y, s2);
      s2 = fma2(q2[6], k3.x, s2); s2 = fma2(q2[7], k3.y, s2);
      float slo, shi; unpack2(s2, slo, shi);
      u64 p2 = pack2(ex2f(slo), ex2f(shi));
      ssum = add2(ssum, p2);
      const ulonglong2* vj = (const ulonglong2*)(vdup + jl * 8);
      ulonglong2 v0 = vj[0], v1 = vj[1], v2 = vj[2], v3 = vj[3];
      acc[0] = fma2(p2, v0.x, acc[0]); acc[1] = fma2(p2, v0.y, acc[1]);
      acc[2] = fma2(p2, v1.x, acc[2]); acc[3] = fma2(p2, v1.y, acc[3]);
      acc[4] = fma2(p2, v2.x, acc[4]); acc[5] = fma2(p2, v2.y, acc[5]);
      acc[6] = fma2(p2, v3.x, acc[6]); acc[7] = fma2(p2, v3.y, acc[7]);
    }
  }

  float slo, shi; unpack2(ssum, slo, shi);
  *(float2*)(pssum + ((whalf * 8 + b) * 8 + n) * HW + i0) = make_float2(slo, shi);
  float* ab = pacc + ((whalf * 8 + b) * 64 + n * 8) * HW + i0;
#pragma unroll
  for (int d = 0; d < 8; d++) {
    float alo, ahi; unpack2(acc[d], alo, ahi);
    *(float2*)(ab + d * HW) = make_float2(alo, ahi);
  }
}

// ---------------------------------------------------------------------------
// Output projection with fused partial merge + softmax division.
// grid (8 b, 2 og, 8 pt), block 256. Writes out channels 64..127.
// ---------------------------------------------------------------------------
__global__ __launch_bounds__(256) void proj_kernel(
    const float* __restrict__ pacc, const float* __restrict__ pssum,
    const float* __restrict__ w, const float* __restrict__ bias,
    float* __restrict__ out) {
  extern __shared__ char smraw[];
  float* invs = (float*)smraw;                     // [8][128] 4KB
  float* xs = (float*)(smraw + 4096);              // [64][128] 32KB
  u64* ws2 = (u64*)(smraw + 4096 + 32768);         // [64][32] 16KB
  int b = blockIdx.x, og = blockIdx.y, pt = blockIdx.z;
  int t = threadIdx.x;
  int p0 = pt * 128;

  for (int i = t; i < 1024; i += 256) {
    int n = i >> 7, pp = i & 127;
    float s = pssum[(b * 8 + n) * HW + p0 + pp] +
              pssum[(64 + b * 8 + n) * HW + p0 + pp];
    invs[i] = 1.f / s;
  }
  for (int i = t; i < 64 * 32; i += 256) {
    int c = i >> 5, o = i & 31;
    float wv = w[(og * 32 + o) * 64 + c];
    ws2[i] = pack2(wv, wv);
  }
  __syncthreads();
  for (int i = t; i < 64 * 128; i += 256) {
    int c = i >> 7, pp = i & 127;
    int idx = (b * 64 + c) * HW + p0 + pp;
    xs[i] = (pacc[idx] + pacc[idx + 512 * HW]) * invs[(c >> 3) * 128 + pp];
  }
  __syncthreads();

  int oi = t >> 5, pi = t & 31;
  u64 acc2[4][2];
#pragma unroll
  for (int a = 0; a < 4; a++) { acc2[a][0] = 0ull; acc2[a][1] = 0ull; }

  for (int c0 = 0; c0 < 64; c0 += 4) {
    u64 xv[4][2], wv[4][4];
#pragma unroll
    for (int cc = 0; cc < 4; cc++) {
      xv[cc][0] = *(const u64*)(xs + (c0 + cc) * 128 + pi * 2);
      xv[cc][1] = *(const u64*)(xs + (c0 + cc) * 128 + 64 + pi * 2);
    }
#pragma unroll
    for (int cc = 0; cc < 4; cc++)
#pragma unroll
      for (int a = 0; a < 4; a++) wv[cc][a] = ws2[(c0 + cc) * 32 + oi * 4 + a];
#pragma unroll
    for (int cc = 0; cc < 4; cc++)
#pragma unroll
      for (int a = 0; a < 4; a++) {
        acc2[a][0] = fma2(wv[cc][a], xv[cc][0], acc2[a][0]);
        acc2[a][1] = fma2(wv[cc][a], xv[cc][1], acc2[a][1]);
      }
  }

#pragma unroll
  for (int a = 0; a < 4; a++) {
    int o = og * 32 + oi * 4 + a;
    float bb = bias[o];
    float* ob = out + (b * 128 + 64 + o) * HW + p0;
#pragma unroll
    for (int k = 0; k < 2; k++) {
      float lo, hi; unpack2(acc2[a][k], lo, hi);
      *(float2*)(ob + 64 * k + pi * 2) = make_float2(lo + bb, hi + bb);
    }
  }
}

// ---------------------------------------------------------------------------
extern "C" void kernel_launch(void* const* d_in, const int* in_sizes, int n_in,
                              void* d_out, int out_size) {
  (void)in_sizes; (void)n_in; (void)out_size;
  const float* x      = (const float*)d_in[0];
  const float* conv_w = (const float*)d_in[1];
  const float* conv_b = (const float*)d_in[2];
  const float* qkv_w  = (const float*)d_in[3];
  const float* qkv_b  = (const float*)d_in[4];
  const float* attn_w = (const float*)d_in[5];
  const float* attn_b = (const float*)d_in[6];
  const float* relw   = (const float*)d_in[7];
  const float* relh   = (const float*)d_in[8];
  float* out = (float*)d_out;

  float *qkv_s = nullptr, *pacc = nullptr, *pssum = nullptr;
  cudaGetSymbolAddress((void**)&qkv_s, g_qkv);
  cudaGetSymbolAddress((void**)&pacc, g_pacc);
  cudaGetSymbolAddress((void**)&pssum, g_pssum);

  const int PREP_SMEM = 49152;
  const int PROJ_SMEM = 4096 + 32768 + 16384;
  cudaFuncSetAttribute(prep_kernel, cudaFuncAttributeMaxDynamicSharedMemorySize, PREP_SMEM);
  cudaFuncSetAttribute(attn_kernel, cudaFuncAttributeMaxDynamicSharedMemorySize, AT_SMEM);
  cudaFuncSetAttribute(proj_kernel, cudaFuncAttributeMaxDynamicSharedMemorySize, PROJ_SMEM);

  prep_kernel<<<512, 256, PREP_SMEM>>>(x, conv_w, conv_b, qkv_w, qkv_b, out, qkv_s);
  attn_kernel<<<dim3(64, 2, 2), 256, AT_SMEM>>>(qkv_s, relw, relh, pacc, pssum);
  proj_kernel<<<dim3(8, 2, 8), 256, PROJ_SMEM>>>(pacc, pssum, attn_w, attn_b, out);
}

// round 6
// speedup vs baseline: 1.3381x; 1.3381x over previous
#include <cuda_runtime.h>

#define HW 1024

// Scratch buffers
__device__ float g_qkv[8 * 192 * HW];        // [b][192][1024]; q pre-scaled by dkh^-0.5*log2e
__device__ float g_convp[4 * 8 * 64 * HW];   // [cs][b][64][1024] conv partial sums (no bias)
__device__ float g_pacc[4 * 8 * 64 * HW];    // [wq][b][64][1024] partial softmax-weighted V sums
__device__ float g_pssum[4 * 8 * 8 * HW];    // [wq][b][n][1024] partial exp sums

typedef unsigned long long u64;

__device__ __forceinline__ u64 fma2(u64 a, u64 b, u64 c) {
  u64 d; asm("fma.rn.f32x2 %0,%1,%2,%3;" : "=l"(d) : "l"(a), "l"(b), "l"(c)); return d;
}
__device__ __forceinline__ u64 add2(u64 a, u64 b) {
  u64 d; asm("add.rn.f32x2 %0,%1,%2;" : "=l"(d) : "l"(a), "l"(b)); return d;
}
__device__ __forceinline__ u64 pack2(float lo, float hi) {
  u64 d; asm("mov.b64 %0,{%1,%2};" : "=l"(d) : "f"(lo), "f"(hi)); return d;
}
__device__ __forceinline__ void unpack2(u64 v, float& lo, float& hi) {
  asm("mov.b64 {%0,%1},%2;" : "=f"(lo), "=f"(hi) : "l"(v));
}
__device__ __forceinline__ float ex2f(float x) {
  float y; asm("ex2.approx.ftz.f32 %0,%1;" : "=f"(y) : "f"(x)); return y;
}

// ---------------------------------------------------------------------------
// Fused prep.
// blocks [0,512): conv3x3 c-split partials. blk -> cs(4) x b(8) x og(16),
//   16 input channels each, FMA2 over vertical pixel pairs, planar staging.
// blocks [512,896): qkv 1x1 projection into g_qkv.
// 256 threads, 48KB dynamic smem, 3 blocks/SM.
// ---------------------------------------------------------------------------
__global__ __launch_bounds__(256, 3) void prep_kernel(
    const float* __restrict__ x,
    const float* __restrict__ conv_w,
    const float* __restrict__ qkv_w, const float* __restrict__ qkv_b,
    float* __restrict__ convp, float* __restrict__ qkv_out) {
  extern __shared__ char smraw[];
  int blk = blockIdx.x;
  int t = threadIdx.x;

  if (blk < 512) {
    // ---------------- conv 3x3 partial: 16 channels ----------------
    // wdup: [4 o][16 c][9] dup u64 (4608B); xs: [8 cc][34][34] planar (36992B)
    u64* wdup = (u64*)smraw;
    float* xs = (float*)(smraw + 4608);
    int cs = blk >> 7;
    int rem = blk & 127;
    int b = rem >> 4, og = rem & 15;
    int cbase = cs * 16;

    // stage weights once: 4 oc x 16 c x 9
    for (int i = t; i < 576; i += 256) {
      int o = i / 144, r2 = i - o * 144;   // r2 = c*9 + k
      float wv = conv_w[(og * 4 + o) * 576 + cbase * 9 + r2];
      wdup[i] = pack2(wv, wv);
    }
    // zero all planes once (halo stays zero forever)
    for (int i = t; i < 9248; i += 256) xs[i] = 0.f;

    int xcol = t & 31, m0 = t >> 5;   // output col; y-pairs m0, m0+8
    u64 acc[4][2];
#pragma unroll
    for (int o = 0; o < 4; o++) { acc[o][0] = 0ull; acc[o][1] = 0ull; }

    for (int chunk = 0; chunk < 2; chunk++) {
      __syncthreads();
      // fill interior: 8 channels x 32 rows x 32 cols, coalesced
#pragma unroll
      for (int cc = 0; cc < 8; cc++) {
        const float* xp = x + (b * 64 + cbase + chunk * 8 + cc) * HW;
#pragma unroll
        for (int rg = 0; rg < 4; rg++) {
          int row = rg * 8 + m0;
          xs[cc * 1156 + (row + 1) * 34 + xcol + 1] = xp[row * 32 + xcol];
        }
      }
      __syncthreads();

#pragma unroll
      for (int cc = 0; cc < 8; cc++) {
        const float* xc = xs + cc * 1156;
        int crel = chunk * 8 + cc;
        u64 pr[2][9];
#pragma unroll
        for (int pi = 0; pi < 2; pi++) {
          int m = m0 + pi * 8;
          const float* base = xc + (2 * m) * 34 + xcol;
#pragma unroll
          for (int kw = 0; kw < 3; kw++) {
            float s0 = base[kw], s1 = base[34 + kw];
            float s2 = base[68 + kw], s3 = base[102 + kw];
            pr[pi][0 + kw] = pack2(s0, s1);
            pr[pi][3 + kw] = pack2(s1, s2);
            pr[pi][6 + kw] = pack2(s2, s3);
          }
        }
        const u64* wc = wdup + crel * 9;
#pragma unroll
        for (int o = 0; o < 4; o++) {
          const u64* wo = wc + o * 144;
          u64 a0 = acc[o][0], a1 = acc[o][1];
#pragma unroll
          for (int k = 0; k < 9; k++) {
            u64 wk = wo[k];
            a0 = fma2(pr[0][k], wk, a0);
            a1 = fma2(pr[1][k], wk, a1);
          }
          acc[o][0] = a0; acc[o][1] = a1;
        }
      }
    }

    float* cpb = convp + (cs * 8 + b) * 64 * HW + og * 4 * HW;
#pragma unroll
    for (int o = 0; o < 4; o++) {
#pragma unroll
      for (int pi = 0; pi < 2; pi++) {
        int m = m0 + pi * 8;
        float lo, hi; unpack2(acc[o][pi], lo, hi);
        cpb[o * HW + (2 * m) * 32 + xcol] = lo;
        cpb[o * HW + (2 * m + 1) * 32 + xcol] = hi;
      }
    }
  } else {
    // ---------------- qkv 1x1 projection ----------------
    float* xs = (float*)smraw;               // [64][128] 32KB
    u64* ws2 = (u64*)(smraw + 32768);        // [64][32]  16KB
    int r = blk - 512;
    int b = r / 48;
    int rem = r - b * 48;
    int og = rem >> 3, pt = rem & 7;
    int p0 = pt * 128;

    for (int i = t; i < 64 * 128; i += 256) {
      int c = i >> 7, pp = i & 127;
      xs[i] = x[(b * 64 + c) * HW + p0 + pp];
    }
    for (int i = t; i < 64 * 32; i += 256) {
      int c = i >> 5, o = i & 31;
      float wv = qkv_w[(og * 32 + o) * 64 + c];
      ws2[i] = pack2(wv, wv);
    }
    __syncthreads();

    int oi = t >> 5, pi = t & 31;
    u64 acc2[4][2];
#pragma unroll
    for (int a = 0; a < 4; a++) { acc2[a][0] = 0ull; acc2[a][1] = 0ull; }

    for (int c0 = 0; c0 < 64; c0 += 4) {
      u64 xv[4][2], wv[4][4];
#pragma unroll
      for (int cc = 0; cc < 4; cc++) {
        xv[cc][0] = *(const u64*)(xs + (c0 + cc) * 128 + pi * 2);
        xv[cc][1] = *(const u64*)(xs + (c0 + cc) * 128 + 64 + pi * 2);
      }
#pragma unroll
      for (int cc = 0; cc < 4; cc++)
#pragma unroll
        for (int a = 0; a < 4; a++) wv[cc][a] = ws2[(c0 + cc) * 32 + oi * 4 + a];
#pragma unroll
      for (int cc = 0; cc < 4; cc++)
#pragma unroll
        for (int a = 0; a < 4; a++) {
          acc2[a][0] = fma2(wv[cc][a], xv[cc][0], acc2[a][0]);
          acc2[a][1] = fma2(wv[cc][a], xv[cc][1], acc2[a][1]);
        }
    }

#pragma unroll
    for (int a = 0; a < 4; a++) {
      int o = og * 32 + oi * 4 + a;
      float bb = qkv_b[o];
      float sc = (o < 64) ? (0.35355339059327373f * 1.4426950408889634f) : 1.f;
      float* ob = qkv_out + (b * 192 + o) * HW + p0;
#pragma unroll
      for (int k = 0; k < 2; k++) {
        float lo, hi; unpack2(acc2[a][k], lo, hi);
        *(float2*)(ob + 64 * k + pi * 2) = make_float2(sc * (lo + bb), sc * (hi + bb));
      }
    }
  }
}

// ---------------------------------------------------------------------------
// Attention partials. grid (64 bn, 2 rowhalf, 4 wquarter), block 256.
// Thread owns row pair (i0,i0+1); block covers j's with w2 in its quarter.
// smem ~54KB -> 4 blocks/SM.
// ---------------------------------------------------------------------------
#define AT_KD    0
#define AT_VD    16384
#define AT_RWT   32768                 // [8 w2l][256 pairs] u64 = 16384
#define AT_RELW  49152                 // 504 floats
#define AT_RELHD (AT_RELW + 2016)      // 504 u64
#define AT_SMEM  (AT_RELHD + 4032)     // 55200 bytes

__global__ __launch_bounds__(256, 4) void attn_kernel(
    const float* __restrict__ qkv,
    const float* __restrict__ relw, const float* __restrict__ relh,
    float* __restrict__ pacc, float* __restrict__ pssum) {
  extern __shared__ char sm[];
  int t = threadIdx.x;
  int bn = blockIdx.x;
  int b = bn >> 3, n = bn & 7;
  int rowhalf = blockIdx.y;
  int wq = blockIdx.z;

  const float* qb = qkv + (b * 192 + n * 8) * HW;
  const float* kb = qkv + (b * 192 + 64 + n * 8) * HW;
  const float* vb = qkv + (b * 192 + 128 + n * 8) * HW;

  // stage this w-quarter of K,V duplicated: jl = h2*8 + w2l
  u64* kdup = (u64*)(sm + AT_KD);
  u64* vdup = (u64*)(sm + AT_VD);
  for (int e = t; e < 2048; e += 256) {
    int jl = e >> 3, d = e & 7;
    int h2 = jl >> 3, w2l = jl & 7;
    int j = h2 * 32 + wq * 8 + w2l;
    float kv = kb[d * HW + j];
    float vv = vb[d * HW + j];
    kdup[jl * 8 + d] = pack2(kv, kv);
    vdup[jl * 8 + d] = pack2(vv, vv);
  }
  float* s_relw = (float*)(sm + AT_RELW);
  for (int e = t; e < 504; e += 256) {
    s_relw[e] = relw[e];
    float rv = relh[e];
    *(u64*)(sm + AT_RELHD + e * 8) = pack2(rv, rv);
  }
  __syncthreads();

  int p = t;
  int i0 = rowhalf * 512 + 2 * p;
  int h1 = i0 >> 5, w1 = i0 & 31;   // even i0: rows share h1, w1 <= 30

  float qlo[8], qhi[8];
  u64 q2[8];
#pragma unroll
  for (int d = 0; d < 8; d++) {
    qlo[d] = qb[d * HW + i0];
    qhi[d] = qb[d * HW + i0 + 1];
    q2[d] = pack2(qlo[d], qhi[d]);
  }

  // per-pair rw table for this quarter, transposed [w2l][pair]
  u64* rwt = (u64*)(sm + AT_RWT);
#pragma unroll
  for (int w2l = 0; w2l < 8; w2l++) {
    int w2 = wq * 8 + w2l;
    const float* r0 = s_relw + (w2 - w1 + 31) * 8;
    const float* r1 = r0 - 8;
    float a = 0.f, c = 0.f;
#pragma unroll
    for (int d = 0; d < 8; d++) { a += qlo[d] * r0[d]; c += qhi[d] * r1[d]; }
    rwt[w2l * 256 + p] = pack2(a, c);
  }

  u64 acc[8], ssum = 0ull;
#pragma unroll
  for (int d = 0; d < 8; d++) acc[d] = 0ull;

  for (int h2 = 0; h2 < 32; h2++) {
    const u64* rhp = (const u64*)(sm + AT_RELHD) + (h2 - h1 + 31) * 8;
    u64 rh2 = 0ull;
#pragma unroll
    for (int d = 0; d < 8; d++) rh2 = fma2(q2[d], rhp[d], rh2);

#pragma unroll
    for (int w2l = 0; w2l < 8; w2l++) {
      int jl = h2 * 8 + w2l;
      const ulonglong2* kj = (const ulonglong2*)(kdup + jl * 8);
      ulonglong2 k0 = kj[0], k1 = kj[1], k2 = kj[2], k3 = kj[3];
      u64 s2 = add2(rwt[w2l * 256 + p], rh2);
      s2 = fma2(q2[0], k0.x, s2); s2 = fma2(q2[1], k0.y, s2);
      s2 = fma2(q2[2], k1.x, s2); s2 = fma2(q2[3], k1.y, s2);
      s2 = fma2(q2[4], k2.x, s2); s2 = fma2(q2[5], k2.y, s2);
      s2 = fma2(q2[6], k3.x, s2); s2 = fma2(q2[7], k3.y, s2);
      float slo, shi; unpack2(s2, slo, shi);
      u64 p2 = pack2(ex2f(slo), ex2f(shi));
      ssum = add2(ssum, p2);
      const ulonglong2* vj = (const ulonglong2*)(vdup + jl * 8);
      ulonglong2 v0 = vj[0], v1 = vj[1], v2 = vj[2], v3 = vj[3];
      acc[0] = fma2(p2, v0.x, acc[0]); acc[1] = fma2(p2, v0.y, acc[1]);
      acc[2] = fma2(p2, v1.x, acc[2]); acc[3] = fma2(p2, v1.y, acc[3]);
      acc[4] = fma2(p2, v2.x, acc[4]); acc[5] = fma2(p2, v2.y, acc[5]);
      acc[6] = fma2(p2, v3.x, acc[6]); acc[7] = fma2(p2, v3.y, acc[7]);
    }
  }

  float slo, shi; unpack2(ssum, slo, shi);
  *(float2*)(pssum + ((wq * 8 + b) * 8 + n) * HW + i0) = make_float2(slo, shi);
  float* ab = pacc + ((wq * 8 + b) * 64 + n * 8) * HW + i0;
#pragma unroll
  for (int d = 0; d < 8; d++) {
    float alo, ahi; unpack2(acc[d], alo, ahi);
    *(float2*)(ab + d * HW) = make_float2(alo, ahi);
  }
}

// ---------------------------------------------------------------------------
// Output projection: merges 4 attn partials + softmax division + GEMM
// (out ch 64..127). og==0 blocks also merge the 4 conv partials (ch 0..63).
// grid (8 b, 2 og, 8 pt), block 256.
// ---------------------------------------------------------------------------
__global__ __launch_bounds__(256) void proj_kernel(
    const float* __restrict__ pacc, const float* __restrict__ pssum,
    const float* __restrict__ convp, const float* __restrict__ conv_b,
    const float* __restrict__ w, const float* __restrict__ bias,
    float* __restrict__ out) {
  extern __shared__ char smraw[];
  float* invs = (float*)smraw;                     // [8][128] 4KB
  float* xs = (float*)(smraw + 4096);              // [64][128] 32KB
  u64* ws2 = (u64*)(smraw + 4096 + 32768);         // [64][32] 16KB
  int b = blockIdx.x, og = blockIdx.y, pt = blockIdx.z;
  int t = threadIdx.x;
  int p0 = pt * 128;

  for (int i = t; i < 1024; i += 256) {
    int n = i >> 7, pp = i & 127;
    int idx = (b * 8 + n) * HW + p0 + pp;
    float s = pssum[idx] + pssum[idx + 64 * HW] +
              pssum[idx + 128 * HW] + pssum[idx + 192 * HW];
    invs[i] = 1.f / s;
  }
  for (int i = t; i < 64 * 32; i += 256) {
    int c = i >> 5, o = i & 31;
    float wv = w[(og * 32 + o) * 64 + c];
    ws2[i] = pack2(wv, wv);
  }
  __syncthreads();
  for (int i = t; i < 64 * 128; i += 256) {
    int c = i >> 7, pp = i & 127;
    int idx = (b * 64 + c) * HW + p0 + pp;
    float s = pacc[idx] + pacc[idx + 512 * HW] +
              pacc[idx + 1024 * HW] + pacc[idx + 1536 * HW];
    xs[i] = s * invs[(c >> 3) * 128 + pp];
  }
  __syncthreads();

  int oi = t >> 5, pi = t & 31;
  u64 acc2[4][2];
#pragma unroll
  for (int a = 0; a < 4; a++) { acc2[a][0] = 0ull; acc2[a][1] = 0ull; }

  for (int c0 = 0; c0 < 64; c0 += 4) {
    u64 xv[4][2], wv[4][4];
#pragma unroll
    for (int cc = 0; cc < 4; cc++) {
      xv[cc][0] = *(const u64*)(xs + (c0 + cc) * 128 + pi * 2);
      xv[cc][1] = *(const u64*)(xs + (c0 + cc) * 128 + 64 + pi * 2);
    }
#pragma unroll
    for (int cc = 0; cc < 4; cc++)
#pragma unroll
      for (int a = 0; a < 4; a++) wv[cc][a] = ws2[(c0 + cc) * 32 + oi * 4 + a];
#pragma unroll
    for (int cc = 0; cc < 4; cc++)
#pragma unroll
      for (int a = 0; a < 4; a++) {
        acc2[a][0] = fma2(wv[cc][a], xv[cc][0], acc2[a][0]);
        acc2[a][1] = fma2(wv[cc][a], xv[cc][1], acc2[a][1]);
      }
  }

#pragma unroll
  for (int a = 0; a < 4; a++) {
    int o = og * 32 + oi * 4 + a;
    float bb = bias[o];
    float* ob = out + (b * 128 + 64 + o) * HW + p0;
#pragma unroll
    for (int k = 0; k < 2; k++) {
      float lo, hi; unpack2(acc2[a][k], lo, hi);
      *(float2*)(ob + 64 * k + pi * 2) = make_float2(lo + bb, hi + bb);
    }
  }

  // conv partial merge (og==0 blocks): out channels 0..63 for this (b, pt)
  if (og == 0) {
    for (int i = t; i < 64 * 128; i += 256) {
      int oc = i >> 7, pp = i & 127;
      int idx = (b * 64 + oc) * HW + p0 + pp;
      float s = convp[idx] + convp[idx + 512 * HW] +
                convp[idx + 1024 * HW] + convp[idx + 1536 * HW];
      out[(b * 128 + oc) * HW + p0 + pp] = s + conv_b[oc];
    }
  }
}

// ---------------------------------------------------------------------------
extern "C" void kernel_launch(void* const* d_in, const int* in_sizes, int n_in,
                              void* d_out, int out_size) {
  (void)in_sizes; (void)n_in; (void)out_size;
  const float* x      = (const float*)d_in[0];
  const float* conv_w = (const float*)d_in[1];
  const float* conv_b = (const float*)d_in[2];
  const float* qkv_w  = (const float*)d_in[3];
  const float* qkv_b  = (const float*)d_in[4];
  const float* attn_w = (const float*)d_in[5];
  const float* attn_b = (const float*)d_in[6];
  const float* relw   = (const float*)d_in[7];
  const float* relh   = (const float*)d_in[8];
  float* out = (float*)d_out;

  float *qkv_s = nullptr, *convp = nullptr, *pacc = nullptr, *pssum = nullptr;
  cudaGetSymbolAddress((void**)&qkv_s, g_qkv);
  cudaGetSymbolAddress((void**)&convp, g_convp);
  cudaGetSymbolAddress((void**)&pacc, g_pacc);
  cudaGetSymbolAddress((void**)&pssum, g_pssum);

  const int PREP_SMEM = 49152;
  const int PROJ_SMEM = 4096 + 32768 + 16384;
  cudaFuncSetAttribute(prep_kernel, cudaFuncAttributeMaxDynamicSharedMemorySize, PREP_SMEM);
  cudaFuncSetAttribute(attn_kernel, cudaFuncAttributeMaxDynamicSharedMemorySize, AT_SMEM);
  cudaFuncSetAttribute(proj_kernel, cudaFuncAttributeMaxDynamicSharedMemorySize, PROJ_SMEM);

  prep_kernel<<<896, 256, PREP_SMEM>>>(x, conv_w, qkv_w, qkv_b, convp, qkv_s);
  attn_kernel<<<dim3(64, 2, 4), 256, AT_SMEM>>>(qkv_s, relw, relh, pacc, pssum);
  proj_kernel<<<dim3(8, 2, 8), 256, PROJ_SMEM>>>(pacc, pssum, convp, conv_b,
                                                 attn_w, attn_b, out);
}